// round 7
// baseline (speedup 1.0000x reference)
#include <cuda_runtime.h>
#include <cuda_bf16.h>
#include <math.h>

#define T_TOK 8192
#define D_DIM 768
#define H_DIM 3072
#define E_NUM 8

// ---------------- device scratch (no allocations allowed) ----------------
__device__ unsigned g_xh[T_TOK * (D_DIM / 2)];          // x hi, k-pair packed bf16x2
__device__ unsigned g_xl[T_TOK * (D_DIM / 2)];          // x lo
__device__ unsigned g_w1h[E_NUM * (D_DIM / 2) * H_DIM]; // W1 hi  [e][kp][n]
__device__ unsigned g_w1l[E_NUM * (D_DIM / 2) * H_DIM];
__device__ unsigned g_w2h[E_NUM * (H_DIM / 2) * D_DIM]; // W2 hi
__device__ unsigned g_w2l[E_NUM * (H_DIM / 2) * D_DIM];
__device__ unsigned g_hh[T_TOK * (H_DIM / 2)];          // hidden hi (compact rows)
__device__ unsigned g_hl[T_TOK * (H_DIM / 2)];
__device__ int   g_gate[T_TOK];
__device__ float g_psel[T_TOK];
__device__ int   g_counts[E_NUM];
__device__ unsigned long long g_probsum_q[E_NUM];
__device__ int   g_off[E_NUM + 1];
__device__ int   g_cursor[E_NUM];
__device__ int   g_perm[T_TOK];

#define PROB_SCALE 4294967296.0

// ---------------- helpers ----------------
__device__ __forceinline__ unsigned pack2(float v0, float v1) {
    return (unsigned)__bfloat16_as_ushort(__float2bfloat16_rn(v0)) |
           ((unsigned)__bfloat16_as_ushort(__float2bfloat16_rn(v1)) << 16);
}
__device__ __forceinline__ void split_pack(float v0, float v1, unsigned& h, unsigned& l) {
    __nv_bfloat16 h0 = __float2bfloat16_rn(v0), h1 = __float2bfloat16_rn(v1);
    h = (unsigned)__bfloat16_as_ushort(h0) | ((unsigned)__bfloat16_as_ushort(h1) << 16);
    l = pack2(v0 - __bfloat162float(h0), v1 - __bfloat162float(h1));
}
__device__ __forceinline__ float gelu_exact(float v) {
    return 0.5f * v * (1.0f + erff(v * 0.70710678118654752f));
}
__device__ __forceinline__ void mma16816(float c[4], const unsigned a[4],
                                         unsigned b0, unsigned b1) {
    asm volatile(
        "mma.sync.aligned.m16n8k16.row.col.f32.bf16.bf16.f32 "
        "{%0,%1,%2,%3}, {%4,%5,%6,%7}, {%8,%9}, {%0,%1,%2,%3};\n"
        : "+f"(c[0]), "+f"(c[1]), "+f"(c[2]), "+f"(c[3])
        : "r"(a[0]), "r"(a[1]), "r"(a[2]), "r"(a[3]), "r"(b0), "r"(b1));
}
__device__ __forceinline__ void cp16(unsigned dst, const void* src) {
    asm volatile("cp.async.cg.shared.global [%0], [%1], 16;\n" :: "r"(dst), "l"(src));
}

// ---------------- K0: zero per-launch accumulators ----------------
__global__ void init_kernel() {
    int i = threadIdx.x;
    if (i < E_NUM) { g_counts[i] = 0; g_probsum_q[i] = 0ull; g_cursor[i] = 0; }
}

// ---------------- K1: routing (1 warp per token) ----------------
__global__ void routing_kernel(const float* __restrict__ x,
                               const float* __restrict__ gw) {
    __shared__ unsigned long long s_probsum[E_NUM];
    __shared__ int                s_counts[E_NUM];
    int tid = threadIdx.x;
    if (tid < E_NUM) { s_probsum[tid] = 0ull; s_counts[tid] = 0; }
    __syncthreads();

    int warp = tid >> 5, lane = tid & 31;
    int t = blockIdx.x * 8 + warp;

    float acc[E_NUM];
#pragma unroll
    for (int e = 0; e < E_NUM; e++) acc[e] = 0.f;
    const float* xr = x + (size_t)t * D_DIM;
    for (int k = lane; k < D_DIM; k += 32) {
        float xv = xr[k];
        const float* g = gw + k * E_NUM;
#pragma unroll
        for (int e = 0; e < E_NUM; e++) acc[e] += xv * g[e];
    }
#pragma unroll
    for (int off = 16; off > 0; off >>= 1) {
#pragma unroll
        for (int e = 0; e < E_NUM; e++)
            acc[e] += __shfl_xor_sync(0xffffffffu, acc[e], off);
    }

    if (lane == 0) {
        float mx = acc[0]; int am = 0;
#pragma unroll
        for (int e = 1; e < E_NUM; e++) if (acc[e] > mx) { mx = acc[e]; am = e; }
        float p[E_NUM]; float s = 0.f;
#pragma unroll
        for (int e = 0; e < E_NUM; e++) { p[e] = expf(acc[e] - mx); s += p[e]; }
        float inv = 1.f / s;
#pragma unroll
        for (int e = 0; e < E_NUM; e++) {
            double pq = (double)(p[e] * inv) * PROB_SCALE;
            atomicAdd(&s_probsum[e], (unsigned long long)(pq + 0.5));
        }
        atomicAdd(&s_counts[am], 1);
        g_gate[t] = am;
        g_psel[t] = p[am] * inv;
    }
    __syncthreads();
    if (tid < E_NUM) {
        if (s_probsum[tid]) atomicAdd(&g_probsum_q[tid], s_probsum[tid]);
        if (s_counts[tid])  atomicAdd(&g_counts[tid], s_counts[tid]);
    }
}

// ---------------- K2: offsets + balance loss + output tail ----------------
__global__ void finalize_kernel(float* __restrict__ out, int out_size) {
    if (threadIdx.x == 0 && blockIdx.x == 0) {
        int off = 0;
#pragma unroll
        for (int e = 0; e < E_NUM; e++) { g_off[e] = off; off += g_counts[e]; }
        g_off[E_NUM] = off;

        float loss = 0.f;
        const float invT = 1.0f / (float)T_TOK;
#pragma unroll
        for (int e = 0; e < E_NUM; e++) {
            float ps = (float)((double)g_probsum_q[e] / PROB_SCALE);
            loss += (ps * invT) * ((float)g_counts[e] * invT);
        }
        loss *= (float)E_NUM;

        int base = T_TOK * D_DIM;
        if (out_size > base) out[base] = loss;
#pragma unroll
        for (int e = 0; e < E_NUM; e++)
            if (out_size > base + 1 + e) out[base + 1 + e] = (float)g_counts[e];
    }
}

// ---------------- K3: per-expert compact permutation ----------------
__global__ void scatter_kernel() {
    int t = blockIdx.x * blockDim.x + threadIdx.x;
    if (t < T_TOK) {
        int e = g_gate[t];
        int pos = atomicAdd(&g_cursor[e], 1);
        g_perm[g_off[e] + pos] = t;
    }
}

// ---------------- K4: convert x -> hi/lo packed ----------------
__global__ void conv_x_kernel(const float* __restrict__ x) {
    int w = blockIdx.x * blockDim.x + threadIdx.x;
    if (w < T_TOK * (D_DIM / 2)) {
        float2 v = ((const float2*)x)[w];
        unsigned h, l; split_pack(v.x, v.y, h, l);
        g_xh[w] = h; g_xl[w] = l;
    }
}

// ---------------- K5: convert weights -> hi/lo k-pair packed ----------------
template <int WHICH>
__global__ void conv_w_kernel(const float* __restrict__ W) {
    constexpr int KHALF = (WHICH == 1) ? D_DIM / 2 : H_DIM / 2;
    constexpr int NDIM  = (WHICH == 1) ? H_DIM : D_DIM;
    unsigned* Wh = (WHICH == 1) ? g_w1h : g_w2h;
    unsigned* Wl = (WHICH == 1) ? g_w1l : g_w2l;
    const long per = (long)KHALF * NDIM;
    const long total = (long)E_NUM * per;
    long w = (long)blockIdx.x * blockDim.x + threadIdx.x;
    if (w < total) {
        int  e  = (int)(w / per);
        long r  = w % per;
        int  kp = (int)(r / NDIM);
        int  n  = (int)(r % NDIM);
        const float* We = W + (size_t)e * 2 * per;
        float v0 = We[(size_t)(2 * kp) * NDIM + n];
        float v1 = We[(size_t)(2 * kp + 1) * NDIM + n];
        unsigned h, l; split_pack(v0, v1, h, l);
        Wh[w] = h; Wl[w] = l;
    }
}

// ---------------- GEMM: 128x128 CTA tile, BK=32, 8 warps, 3-stage pipeline ----
// Per-stage smem layout (u32 words):
//   AsH [128][20] off 0 | AsL off 2560 | BsH [16][136] off 5120 | BsL off 7296
#define OFF_AL 2560
#define OFF_BH 5120
#define OFF_BL 7296
#define STAGE_WORDS 9472
#define NSTAGE 3
#define SMEM_BYTES (NSTAGE * STAGE_WORDS * 4)

template <int MODE>   // 1: x @ W1 -> gelu -> hidden(hi/lo)   2: hidden @ W2 -> out
__global__ void __launch_bounds__(256) moe_gemm(const float* __restrict__ bias_in,
                                                float* __restrict__ outp) {
    constexpr int KDIM = (MODE == 1) ? D_DIM : H_DIM;
    constexpr int NDIM = (MODE == 1) ? H_DIM : D_DIM;
    constexpr int ASTRIDE = KDIM / 2;
    constexpr int S = KDIM / 32;

    extern __shared__ unsigned smem[];
    const int e  = blockIdx.z;
    const int ne = g_off[e + 1] - g_off[e];
    const int m0 = blockIdx.y * 128;
    if (m0 >= ne) return;
    const int base = g_off[e];
    const int n0 = blockIdx.x * 128;
    const int tid = threadIdx.x;

    const unsigned* Ah = (MODE == 1) ? g_xh : g_hh;
    const unsigned* Al = (MODE == 1) ? g_xl : g_hl;
    const unsigned* Bh = ((MODE == 1) ? g_w1h : g_w2h) + (size_t)e * ASTRIDE * NDIM;
    const unsigned* Bl = ((MODE == 1) ? g_w1l : g_w2l) + (size_t)e * ASTRIDE * NDIM;
    const float* bias = bias_in + (size_t)e * NDIM;

    // ---- per-thread copy mapping ----
    const int r0 = tid >> 2, kq = (tid & 3) * 4;   // A rows r0, r0+64; 4-u32 chunk
    const int r1 = r0 + 64;
    int ma0 = m0 + r0; if (ma0 >= ne) ma0 = ne - 1;
    int ma1 = m0 + r1; if (ma1 >= ne) ma1 = ne - 1;
    size_t arow0, arow1;
    if (MODE == 1) { arow0 = (size_t)g_perm[base + ma0]; arow1 = (size_t)g_perm[base + ma1]; }
    else           { arow0 = (size_t)(base + ma0);       arow1 = (size_t)(base + ma1); }
    const unsigned* aH0 = Ah + arow0 * ASTRIDE + kq;
    const unsigned* aH1 = Ah + arow1 * ASTRIDE + kq;
    const unsigned* aL0 = Al + arow0 * ASTRIDE + kq;
    const unsigned* aL1 = Al + arow1 * ASTRIDE + kq;

    const int kpA = tid >> 5, kpB = kpA + 8, nq = (tid & 31) * 4;
    const unsigned* bH0 = Bh + (size_t)kpA * NDIM + n0 + nq;
    const unsigned* bH1 = Bh + (size_t)kpB * NDIM + n0 + nq;
    const unsigned* bL0 = Bl + (size_t)kpA * NDIM + n0 + nq;
    const unsigned* bL1 = Bl + (size_t)kpB * NDIM + n0 + nq;

    const unsigned sbase = (unsigned)__cvta_generic_to_shared(smem);
    const unsigned dA0 = (r0 * 20 + kq) * 4u, dA1 = (r1 * 20 + kq) * 4u;
    const unsigned dB0 = (kpA * 136 + nq) * 4u, dB1 = (kpB * 136 + nq) * 4u;

    auto issue = [&](int buf) {
        unsigned o = sbase + buf * (STAGE_WORDS * 4u);
        cp16(o + dA0, aH0);                 cp16(o + dA1, aH1);
        cp16(o + OFF_AL * 4u + dA0, aL0);   cp16(o + OFF_AL * 4u + dA1, aL1);
        cp16(o + OFF_BH * 4u + dB0, bH0);   cp16(o + OFF_BH * 4u + dB1, bH1);
        cp16(o + OFF_BL * 4u + dB0, bL0);   cp16(o + OFF_BL * 4u + dB1, bL1);
        asm volatile("cp.async.commit_group;\n");
        aH0 += 16; aH1 += 16; aL0 += 16; aL1 += 16;
        bH0 += (size_t)16 * NDIM; bH1 += (size_t)16 * NDIM;
        bL0 += (size_t)16 * NDIM; bL1 += (size_t)16 * NDIM;
    };

    // ---- warp / fragment mapping ----
    const int wid = tid >> 5, lane = tid & 31;
    const int grp = lane >> 2, tig = lane & 3;
    const int wm = (wid >> 1) * 32, wn = (wid & 1) * 64;

    float acc[2][8][4];
#pragma unroll
    for (int mi = 0; mi < 2; mi++)
#pragma unroll
        for (int ni = 0; ni < 8; ni++)
#pragma unroll
            for (int j = 0; j < 4; j++) acc[mi][ni][j] = 0.f;

    // prefetch two stages ahead
    issue(0);
    issue(1);

    for (int s = 0; s < S; s++) {
        if (s + 1 < S) asm volatile("cp.async.wait_group 1;\n");
        else           asm volatile("cp.async.wait_group 0;\n");
        __syncthreads();                      // stage s ready; all warps done with s-1
        if (s + 2 < S) issue((s + 2) % NSTAGE);   // refill buffer last used by s-1

        const unsigned* As_h = smem + (s % NSTAGE) * STAGE_WORDS;
        const unsigned* As_l = As_h + OFF_AL;
        const unsigned* Bs_h = As_h + OFF_BH;
        const unsigned* Bs_l = As_h + OFF_BL;

#pragma unroll
        for (int h = 0; h < 2; h++) {
            const int kb = h * 8;
            unsigned ah[2][4], al[2][4];
#pragma unroll
            for (int mi = 0; mi < 2; mi++) {
                int row = wm + mi * 16 + grp;
                ah[mi][0] = As_h[row * 20 + kb + tig];
                ah[mi][1] = As_h[(row + 8) * 20 + kb + tig];
                ah[mi][2] = As_h[row * 20 + kb + tig + 4];
                ah[mi][3] = As_h[(row + 8) * 20 + kb + tig + 4];
                al[mi][0] = As_l[row * 20 + kb + tig];
                al[mi][1] = As_l[(row + 8) * 20 + kb + tig];
                al[mi][2] = As_l[row * 20 + kb + tig + 4];
                al[mi][3] = As_l[(row + 8) * 20 + kb + tig + 4];
            }
#pragma unroll
            for (int ni = 0; ni < 8; ni++) {
                int nc = wn + ni * 8 + grp;
                unsigned bh0 = Bs_h[(kb + tig) * 136 + nc];
                unsigned bh1 = Bs_h[(kb + tig + 4) * 136 + nc];
                unsigned bl0 = Bs_l[(kb + tig) * 136 + nc];
                unsigned bl1 = Bs_l[(kb + tig + 4) * 136 + nc];
#pragma unroll
                for (int mi = 0; mi < 2; mi++) {
                    mma16816(acc[mi][ni], ah[mi], bh0, bh1);
                    mma16816(acc[mi][ni], ah[mi], bl0, bl1);
                    mma16816(acc[mi][ni], al[mi], bh0, bh1);
                }
            }
        }
    }

    // ---- epilogue ----
#pragma unroll
    for (int mi = 0; mi < 2; mi++) {
#pragma unroll
        for (int ni = 0; ni < 8; ni++) {
            const int mloc = m0 + wm + mi * 16 + grp;
            const int nc = n0 + wn + ni * 8 + tig * 2;
            const float* ac = acc[mi][ni];
            if (MODE == 1) {
                if (mloc < ne) {
                    float v0 = gelu_exact(ac[0] + bias[nc]);
                    float v1 = gelu_exact(ac[1] + bias[nc + 1]);
                    unsigned hw, lw; split_pack(v0, v1, hw, lw);
                    size_t idx = (size_t)(base + mloc) * (H_DIM / 2) + (nc >> 1);
                    g_hh[idx] = hw; g_hl[idx] = lw;
                }
                if (mloc + 8 < ne) {
                    float v0 = gelu_exact(ac[2] + bias[nc]);
                    float v1 = gelu_exact(ac[3] + bias[nc + 1]);
                    unsigned hw, lw; split_pack(v0, v1, hw, lw);
                    size_t idx = (size_t)(base + mloc + 8) * (H_DIM / 2) + (nc >> 1);
                    g_hh[idx] = hw; g_hl[idx] = lw;
                }
            } else {
                if (mloc < ne) {
                    int tok = g_perm[base + mloc]; float ps = g_psel[tok];
                    float2 v = make_float2((ac[0] + bias[nc]) * ps,
                                           (ac[1] + bias[nc + 1]) * ps);
                    *(float2*)&outp[(size_t)tok * D_DIM + nc] = v;
                }
                if (mloc + 8 < ne) {
                    int tok = g_perm[base + mloc + 8]; float ps = g_psel[tok];
                    float2 v = make_float2((ac[2] + bias[nc]) * ps,
                                           (ac[3] + bias[nc + 1]) * ps);
                    *(float2*)&outp[(size_t)tok * D_DIM + nc] = v;
                }
            }
        }
    }
}

// ---------------- launch ----------------
extern "C" void kernel_launch(void* const* d_in, const int* in_sizes, int n_in,
                              void* d_out, int out_size) {
    const float* x  = (const float*)d_in[0];
    const float* gw = (const float*)d_in[2];
    const float* W1 = (const float*)d_in[3];
    const float* b1 = (const float*)d_in[4];
    const float* W2 = (const float*)d_in[5];
    const float* b2 = (const float*)d_in[6];
    float* out = (float*)d_out;

    cudaFuncSetAttribute(moe_gemm<1>, cudaFuncAttributeMaxDynamicSharedMemorySize, SMEM_BYTES);
    cudaFuncSetAttribute(moe_gemm<2>, cudaFuncAttributeMaxDynamicSharedMemorySize, SMEM_BYTES);

    init_kernel<<<1, 32>>>();
    routing_kernel<<<T_TOK / 8, 256>>>(x, gw);
    finalize_kernel<<<1, 32>>>(out, out_size);
    scatter_kernel<<<T_TOK / 256, 256>>>();

    conv_x_kernel<<<(T_TOK * (D_DIM / 2)) / 256, 256>>>(x);
    conv_w_kernel<1><<<(E_NUM * (D_DIM / 2) * H_DIM) / 256, 256>>>(W1);
    conv_w_kernel<2><<<(E_NUM * (H_DIM / 2) * D_DIM) / 256, 256>>>(W2);

    dim3 g1(H_DIM / 128, T_TOK / 128, E_NUM);
    moe_gemm<1><<<g1, 256, SMEM_BYTES>>>(b1, nullptr);

    dim3 g2(D_DIM / 128, T_TOK / 128, E_NUM);
    moe_gemm<2><<<g2, 256, SMEM_BYTES>>>(b2, out);
}

// round 8
// speedup vs baseline: 2.1607x; 2.1607x over previous
#include <cuda_runtime.h>
#include <cuda_fp16.h>
#include <math.h>

#define T_TOK 8192
#define D_DIM 768
#define H_DIM 3072
#define E_NUM 8

// ---------------- device scratch (no allocations allowed) ----------------
__device__ unsigned g_xh[T_TOK * (D_DIM / 2)];          // x fp16, k-pair packed
__device__ unsigned g_w1h[E_NUM * (D_DIM / 2) * H_DIM]; // W1 fp16 [e][kp][n]
__device__ unsigned g_w2h[E_NUM * (H_DIM / 2) * D_DIM]; // W2 fp16
__device__ unsigned g_hh[T_TOK * (H_DIM / 2)];          // hidden fp16 (compact rows)
__device__ int   g_gate[T_TOK];
__device__ float g_psel[T_TOK];
__device__ int   g_counts[E_NUM];
__device__ unsigned long long g_probsum_q[E_NUM];
__device__ int   g_off[E_NUM + 1];
__device__ int   g_cursor[E_NUM];
__device__ int   g_perm[T_TOK];

#define PROB_SCALE 4294967296.0

// ---------------- helpers ----------------
__device__ __forceinline__ unsigned pack2h(float v0, float v1) {
    __half2 h = __floats2half2_rn(v0, v1);
    return *(unsigned*)&h;
}
__device__ __forceinline__ float gelu_exact(float v) {
    return 0.5f * v * (1.0f + erff(v * 0.70710678118654752f));
}
__device__ __forceinline__ void mma16816h(float c[4], const unsigned a[4],
                                          unsigned b0, unsigned b1) {
    asm volatile(
        "mma.sync.aligned.m16n8k16.row.col.f32.f16.f16.f32 "
        "{%0,%1,%2,%3}, {%4,%5,%6,%7}, {%8,%9}, {%0,%1,%2,%3};\n"
        : "+f"(c[0]), "+f"(c[1]), "+f"(c[2]), "+f"(c[3])
        : "r"(a[0]), "r"(a[1]), "r"(a[2]), "r"(a[3]), "r"(b0), "r"(b1));
}
__device__ __forceinline__ void cp16(unsigned dst, const void* src) {
    asm volatile("cp.async.cg.shared.global [%0], [%1], 16;\n" :: "r"(dst), "l"(src));
}

// ---------------- K0: zero per-launch accumulators ----------------
__global__ void init_kernel() {
    int i = threadIdx.x;
    if (i < E_NUM) { g_counts[i] = 0; g_probsum_q[i] = 0ull; g_cursor[i] = 0; }
}

// ---------------- K1: routing (1 warp per token, fp32) ----------------
__global__ void routing_kernel(const float* __restrict__ x,
                               const float* __restrict__ gw) {
    __shared__ unsigned long long s_probsum[E_NUM];
    __shared__ int                s_counts[E_NUM];
    int tid = threadIdx.x;
    if (tid < E_NUM) { s_probsum[tid] = 0ull; s_counts[tid] = 0; }
    __syncthreads();

    int warp = tid >> 5, lane = tid & 31;
    int t = blockIdx.x * 8 + warp;

    float acc[E_NUM];
#pragma unroll
    for (int e = 0; e < E_NUM; e++) acc[e] = 0.f;
    const float* xr = x + (size_t)t * D_DIM;
    for (int k = lane; k < D_DIM; k += 32) {
        float xv = xr[k];
        const float* g = gw + k * E_NUM;
#pragma unroll
        for (int e = 0; e < E_NUM; e++) acc[e] += xv * g[e];
    }
#pragma unroll
    for (int off = 16; off > 0; off >>= 1) {
#pragma unroll
        for (int e = 0; e < E_NUM; e++)
            acc[e] += __shfl_xor_sync(0xffffffffu, acc[e], off);
    }

    if (lane == 0) {
        float mx = acc[0]; int am = 0;
#pragma unroll
        for (int e = 1; e < E_NUM; e++) if (acc[e] > mx) { mx = acc[e]; am = e; }
        float p[E_NUM]; float s = 0.f;
#pragma unroll
        for (int e = 0; e < E_NUM; e++) { p[e] = expf(acc[e] - mx); s += p[e]; }
        float inv = 1.f / s;
#pragma unroll
        for (int e = 0; e < E_NUM; e++) {
            double pq = (double)(p[e] * inv) * PROB_SCALE;
            atomicAdd(&s_probsum[e], (unsigned long long)(pq + 0.5));
        }
        atomicAdd(&s_counts[am], 1);
        g_gate[t] = am;
        g_psel[t] = p[am] * inv;
    }
    __syncthreads();
    if (tid < E_NUM) {
        if (s_probsum[tid]) atomicAdd(&g_probsum_q[tid], s_probsum[tid]);
        if (s_counts[tid])  atomicAdd(&g_counts[tid], s_counts[tid]);
    }
}

// ---------------- K2: offsets + balance loss + output tail ----------------
__global__ void finalize_kernel(float* __restrict__ out, int out_size) {
    if (threadIdx.x == 0 && blockIdx.x == 0) {
        int off = 0;
#pragma unroll
        for (int e = 0; e < E_NUM; e++) { g_off[e] = off; off += g_counts[e]; }
        g_off[E_NUM] = off;

        float loss = 0.f;
        const float invT = 1.0f / (float)T_TOK;
#pragma unroll
        for (int e = 0; e < E_NUM; e++) {
            float ps = (float)((double)g_probsum_q[e] / PROB_SCALE);
            loss += (ps * invT) * ((float)g_counts[e] * invT);
        }
        loss *= (float)E_NUM;

        int base = T_TOK * D_DIM;
        if (out_size > base) out[base] = loss;
#pragma unroll
        for (int e = 0; e < E_NUM; e++)
            if (out_size > base + 1 + e) out[base + 1 + e] = (float)g_counts[e];
    }
}

// ---------------- K3: per-expert compact permutation ----------------
__global__ void scatter_kernel() {
    int t = blockIdx.x * blockDim.x + threadIdx.x;
    if (t < T_TOK) {
        int e = g_gate[t];
        int pos = atomicAdd(&g_cursor[e], 1);
        g_perm[g_off[e] + pos] = t;
    }
}

// ---------------- K4: convert x -> fp16 pairs ----------------
__global__ void conv_x_kernel(const float* __restrict__ x) {
    int w = blockIdx.x * blockDim.x + threadIdx.x;
    if (w < T_TOK * (D_DIM / 2)) {
        float2 v = ((const float2*)x)[w];
        g_xh[w] = pack2h(v.x, v.y);
    }
}

// ---------------- K5: convert weights -> fp16 k-pair packed ----------------
template <int WHICH>
__global__ void conv_w_kernel(const float* __restrict__ W) {
    constexpr int KHALF = (WHICH == 1) ? D_DIM / 2 : H_DIM / 2;
    constexpr int NDIM  = (WHICH == 1) ? H_DIM : D_DIM;
    unsigned* Wh = (WHICH == 1) ? g_w1h : g_w2h;
    const long per = (long)KHALF * NDIM;
    const long total = (long)E_NUM * per;
    long w = (long)blockIdx.x * blockDim.x + threadIdx.x;
    if (w < total) {
        int  e  = (int)(w / per);
        long r  = w % per;
        int  kp = (int)(r / NDIM);
        int  n  = (int)(r % NDIM);
        const float* We = W + (size_t)e * 2 * per;
        float v0 = We[(size_t)(2 * kp) * NDIM + n];
        float v1 = We[(size_t)(2 * kp + 1) * NDIM + n];
        Wh[w] = pack2h(v0, v1);
    }
}

// ---------------- GEMM: 128x128 CTA tile, BK=32, 8 warps, fp16, 3-stage ----
// Per-stage smem (u32 words): As [128][20] off 0 | Bs [16][136] off 2560
#define OFF_B 2560
#define STAGE_WORDS 4736
#define NSTAGE 3
#define SMEM_BYTES (NSTAGE * STAGE_WORDS * 4)

template <int MODE>   // 1: x @ W1 -> gelu -> hidden(fp16)   2: hidden @ W2 -> out
__global__ void __launch_bounds__(256, 2) moe_gemm(const float* __restrict__ bias_in,
                                                   float* __restrict__ outp) {
    constexpr int KDIM = (MODE == 1) ? D_DIM : H_DIM;
    constexpr int NDIM = (MODE == 1) ? H_DIM : D_DIM;
    constexpr int ASTRIDE = KDIM / 2;
    constexpr int S = KDIM / 32;

    extern __shared__ unsigned smem[];
    const int e  = blockIdx.z;
    const int ne = g_off[e + 1] - g_off[e];
    const int m0 = blockIdx.y * 128;
    if (m0 >= ne) return;
    const int base = g_off[e];
    const int n0 = blockIdx.x * 128;
    const int tid = threadIdx.x;

    const unsigned* Ah = (MODE == 1) ? g_xh : g_hh;
    const unsigned* Bh = ((MODE == 1) ? g_w1h : g_w2h) + (size_t)e * ASTRIDE * NDIM;
    const float* bias = bias_in + (size_t)e * NDIM;

    // ---- per-thread copy mapping ----
    // A: 128 rows x 16 u32; thread -> rows r0, r0+64, 16B chunk kq
    const int r0 = tid >> 2, kq = (tid & 3) * 4;
    const int r1 = r0 + 64;
    int ma0 = m0 + r0; if (ma0 >= ne) ma0 = ne - 1;
    int ma1 = m0 + r1; if (ma1 >= ne) ma1 = ne - 1;
    size_t arow0, arow1;
    if (MODE == 1) { arow0 = (size_t)g_perm[base + ma0]; arow1 = (size_t)g_perm[base + ma1]; }
    else           { arow0 = (size_t)(base + ma0);       arow1 = (size_t)(base + ma1); }
    const unsigned* aH0 = Ah + arow0 * ASTRIDE + kq;
    const unsigned* aH1 = Ah + arow1 * ASTRIDE + kq;

    // B: 16 kp-rows x 128 n; thread -> kp rows kpA, kpA+8, 16B chunk nq
    const int kpA = tid >> 5, kpB = kpA + 8, nq = (tid & 31) * 4;
    const unsigned* bH0 = Bh + (size_t)kpA * NDIM + n0 + nq;
    const unsigned* bH1 = Bh + (size_t)kpB * NDIM + n0 + nq;

    const unsigned sbase = (unsigned)__cvta_generic_to_shared(smem);
    const unsigned dA0 = (r0 * 20 + kq) * 4u, dA1 = (r1 * 20 + kq) * 4u;
    const unsigned dB0 = (kpA * 136 + nq) * 4u, dB1 = (kpB * 136 + nq) * 4u;

    auto issue = [&](int buf) {
        unsigned o = sbase + buf * (STAGE_WORDS * 4u);
        cp16(o + dA0, aH0);
        cp16(o + dA1, aH1);
        cp16(o + OFF_B * 4u + dB0, bH0);
        cp16(o + OFF_B * 4u + dB1, bH1);
        asm volatile("cp.async.commit_group;\n");
        aH0 += 16; aH1 += 16;
        bH0 += (size_t)16 * NDIM; bH1 += (size_t)16 * NDIM;
    };

    // ---- warp / fragment mapping ----
    const int wid = tid >> 5, lane = tid & 31;
    const int grp = lane >> 2, tig = lane & 3;
    const int wm = (wid >> 1) * 32, wn = (wid & 1) * 64;

    float acc[2][8][4];
#pragma unroll
    for (int mi = 0; mi < 2; mi++)
#pragma unroll
        for (int ni = 0; ni < 8; ni++)
#pragma unroll
            for (int j = 0; j < 4; j++) acc[mi][ni][j] = 0.f;

    issue(0);
    issue(1);

    for (int s = 0; s < S; s++) {
        if (s + 1 < S) asm volatile("cp.async.wait_group 1;\n");
        else           asm volatile("cp.async.wait_group 0;\n");
        __syncthreads();
        if (s + 2 < S) issue((s + 2) % NSTAGE);

        const unsigned* As = smem + (s % NSTAGE) * STAGE_WORDS;
        const unsigned* Bs = As + OFF_B;

#pragma unroll
        for (int h = 0; h < 2; h++) {
            const int kb = h * 8;
            unsigned ah[2][4];
#pragma unroll
            for (int mi = 0; mi < 2; mi++) {
                int row = wm + mi * 16 + grp;
                ah[mi][0] = As[row * 20 + kb + tig];
                ah[mi][1] = As[(row + 8) * 20 + kb + tig];
                ah[mi][2] = As[row * 20 + kb + tig + 4];
                ah[mi][3] = As[(row + 8) * 20 + kb + tig + 4];
            }
#pragma unroll
            for (int ni = 0; ni < 8; ni++) {
                int nc = wn + ni * 8 + grp;
                unsigned b0 = Bs[(kb + tig) * 136 + nc];
                unsigned b1 = Bs[(kb + tig + 4) * 136 + nc];
#pragma unroll
                for (int mi = 0; mi < 2; mi++)
                    mma16816h(acc[mi][ni], ah[mi], b0, b1);
            }
        }
    }

    // ---- epilogue ----
#pragma unroll
    for (int mi = 0; mi < 2; mi++) {
#pragma unroll
        for (int ni = 0; ni < 8; ni++) {
            const int mloc = m0 + wm + mi * 16 + grp;
            const int nc = n0 + wn + ni * 8 + tig * 2;
            const float* ac = acc[mi][ni];
            if (MODE == 1) {
                if (mloc < ne) {
                    float v0 = gelu_exact(ac[0] + bias[nc]);
                    float v1 = gelu_exact(ac[1] + bias[nc + 1]);
                    g_hh[(size_t)(base + mloc) * (H_DIM / 2) + (nc >> 1)] = pack2h(v0, v1);
                }
                if (mloc + 8 < ne) {
                    float v0 = gelu_exact(ac[2] + bias[nc]);
                    float v1 = gelu_exact(ac[3] + bias[nc + 1]);
                    g_hh[(size_t)(base + mloc + 8) * (H_DIM / 2) + (nc >> 1)] = pack2h(v0, v1);
                }
            } else {
                if (mloc < ne) {
                    int tok = g_perm[base + mloc]; float ps = g_psel[tok];
                    float2 v = make_float2((ac[0] + bias[nc]) * ps,
                                           (ac[1] + bias[nc + 1]) * ps);
                    *(float2*)&outp[(size_t)tok * D_DIM + nc] = v;
                }
                if (mloc + 8 < ne) {
                    int tok = g_perm[base + mloc + 8]; float ps = g_psel[tok];
                    float2 v = make_float2((ac[2] + bias[nc]) * ps,
                                           (ac[3] + bias[nc + 1]) * ps);
                    *(float2*)&outp[(size_t)tok * D_DIM + nc] = v;
                }
            }
        }
    }
}

// ---------------- launch ----------------
extern "C" void kernel_launch(void* const* d_in, const int* in_sizes, int n_in,
                              void* d_out, int out_size) {
    const float* x  = (const float*)d_in[0];
    const float* gw = (const float*)d_in[2];
    const float* W1 = (const float*)d_in[3];
    const float* b1 = (const float*)d_in[4];
    const float* W2 = (const float*)d_in[5];
    const float* b2 = (const float*)d_in[6];
    float* out = (float*)d_out;

    cudaFuncSetAttribute(moe_gemm<1>, cudaFuncAttributeMaxDynamicSharedMemorySize, SMEM_BYTES);
    cudaFuncSetAttribute(moe_gemm<2>, cudaFuncAttributeMaxDynamicSharedMemorySize, SMEM_BYTES);

    init_kernel<<<1, 32>>>();
    routing_kernel<<<T_TOK / 8, 256>>>(x, gw);
    finalize_kernel<<<1, 32>>>(out, out_size);
    scatter_kernel<<<T_TOK / 256, 256>>>();

    conv_x_kernel<<<(T_TOK * (D_DIM / 2)) / 256, 256>>>(x);
    conv_w_kernel<1><<<(E_NUM * (D_DIM / 2) * H_DIM) / 256, 256>>>(W1);
    conv_w_kernel<2><<<(E_NUM * (H_DIM / 2) * D_DIM) / 256, 256>>>(W2);

    dim3 g1(H_DIM / 128, T_TOK / 128, E_NUM);
    moe_gemm<1><<<g1, 256, SMEM_BYTES>>>(b1, nullptr);

    dim3 g2(D_DIM / 128, T_TOK / 128, E_NUM);
    moe_gemm<2><<<g2, 256, SMEM_BYTES>>>(b2, out);
}